// round 14
// baseline (speedup 1.0000x reference)
#include <cuda_runtime.h>
#include <math.h>

#define Bb      128
#define Ll      2048
#define NOBS    32
#define NHID    512
#define NSTEPS  (Ll - 1)          // 2047
#define NCTA    128
#define NTHREADS 128
typedef unsigned long long u64;
typedef unsigned int u32;
#define NBUMPS  ((u32)(NSTEPS - 1))   // 2046 bumps per warp per replay

// SMEM: only A interleaved [256 k2][16 q][4 floats]
#define SA2_FLOATS (256 * 16 * 4)               // 65536 B
#define SMEM_BYTES (SA2_FLOATS * 4)

// per-(m-tile, warp, n-tile) producer flags; one 128B line per (mt,w)
__device__ __align__(128) u32 g_flags[8][4][32];

// ---------------------------------------------------------------------------
__device__ __forceinline__ u64 pack2(float a, float b) {
    u64 r;
    asm("mov.b64 %0, {%1, %2};" : "=l"(r) : "f"(a), "f"(b));
    return r;
}
__device__ __forceinline__ void unpack2(u64 v, float& a, float& b) {
    asm("mov.b64 {%0, %1}, %2;" : "=f"(a), "=f"(b) : "l"(v));
}
__device__ __forceinline__ void ffma2(u64& acc, u64 a, u64 x) {
    asm("fma.rn.f32x2 %0, %1, %2, %0;" : "+l"(acc) : "l"(a), "l"(x));
}
__device__ __forceinline__ u64 acq64(const u32* p) {
    u64 v;
    asm volatile("ld.global.acquire.gpu.u64 %0, [%1];" : "=l"(v) : "l"(p));
    return v;
}
__device__ __forceinline__ u32 acq32(const u32* p) {
    u32 v;
    asm volatile("ld.global.acquire.gpu.u32 %0, [%1];" : "=r"(v) : "l"(p));
    return v;
}
// spin until both u32 halves at f2 (8B-aligned) reach bt
__device__ __forceinline__ void wait2(const u32* f2, u32 bt) {
    u64 v = acq64(f2);
    while ((u32)v < bt || (u32)(v >> 32) < bt) v = acq64(f2);
}

// XLA EmitFastTanh (fma path) — verified bit-exact (rel_err 0.0). DO NOT CHANGE.
__device__ __forceinline__ float tanh_xla(float x) {
    const float kClamp = 7.99881172180175781f;
    float xc = fminf(fmaxf(x, -kClamp), kClamp);
    float x2 = __fmul_rn(xc, xc);
    float num = -2.76076847742355e-16f;
    num = fmaf(x2, num, 2.00018790482477e-13f);
    num = fmaf(x2, num, -8.60467152213735e-11f);
    num = fmaf(x2, num, 5.12229709037114e-08f);
    num = fmaf(x2, num, 1.48572235717979e-05f);
    num = fmaf(x2, num, 6.37261928875436e-04f);
    num = fmaf(x2, num, 4.89352455891786e-03f);
    num = __fmul_rn(xc, num);
    float den = 1.19825839466702e-06f;
    den = fmaf(x2, den, 1.18534705686654e-04f);
    den = fmaf(x2, den, 2.26843463243900e-03f);
    den = fmaf(x2, den, 4.89352518554385e-03f);
    float r = __fdiv_rn(num, den);
    return (fabsf(x) < 0.0004f) ? x : r;
}

// per-lane X chunk registers: [slot 0/1][vA@k, vA@k+1, vB@k, vB@k+1]
struct XChunk { float v[2][4]; };

// ---------------------------------------------------------------------------
// Persistent HCNN scan, order-exact fp32, warp-autonomous, REGISTER-X + SHFL.
// 128 CTAs = 16 n-tiles (32 cols) x 8 m-tiles. Warp w owns pairs {2w, 2w+1};
// lane: p2 = l>>4 (pair half), q = l&15 (col-pair). Per 64-k chunk c, lane
// holds X for k2 = 32c + 16s + q of ITS pair (slot s = 0,1) in registers,
// loaded by coalesced LDG directly from `states` (no SMEM X, no STS, no
// syncwarp). Compute broadcasts X[k2] via shfl from lane (k2&15)+16*p2.
// A stays in SMEM (same sA2 layout). ffma2 chain values + order identical
// to the bit-exact R13 kernel.
// ---------------------------------------------------------------------------
__global__ void __launch_bounds__(NTHREADS, 1) ptf_persistent(
    const float* __restrict__ data,   // [B, L, NOBS]
    const float* __restrict__ Amat,   // [NHID, NHID]
    const float* __restrict__ h0,     // [NHID]
    float* __restrict__ exps,
    float* __restrict__ states,       // doubles as the recurrent state
    float* __restrict__ deltas,
    float* __restrict__ partials)
{
    extern __shared__ char smem_raw[];
    float* sA2 = (float*)smem_raw;                        // [256][16][4]

    const int tid = threadIdx.x;
    const int w   = tid >> 5;
    const int l   = tid & 31;
    const int nt  = blockIdx.x & 15;
    const int mt  = blockIdx.x >> 4;
    const int n0  = nt * 32;
    const int m0  = mt * 16;

    const u32* flagrow = &g_flags[mt][w][0];
    u32* myflag = &g_flags[mt][w][nt];
    u32 base = acq32(myflag);
    base -= base % NBUMPS;                 // monotonic across graph replays

    // ---- one-time: A -> sA2[k2][q][4] = {a_n[2k2],a_n[2k2+1],a_n1[2k2],a_n1[2k2+1]}
    for (int i = tid; i < 256 * 16; i += NTHREADS) {
        const int k2 = i >> 4;
        const int q  = i & 15;
        const int n  = n0 + 2 * q;
        float2 a0 = *(const float2*)&Amat[(size_t)n * NHID + 2 * k2];
        float2 a1 = *(const float2*)&Amat[(size_t)(n + 1) * NHID + 2 * k2];
        *(float4*)&sA2[(size_t)i * 4] = make_float4(a0.x, a0.y, a1.x, a1.y);
    }
    __syncthreads();                       // only CTA-wide sync in the kernel

    // lane identifiers
    const int p2 = l >> 4;                 // pair half 0/1
    const int q  = l & 15;                 // col-pair / k2-lane index
    const int P  = 2 * w + p2;             // this lane's pair
    const int bA = m0 + P;                 // batches bA, bA+8
    const int bB = bA + 8;
    const int nA = n0 + 2 * q;             // compute cols nA, nA+1
    const int shfl_base = p2 << 4;

    for (int t = 0; t < NSTEPS; t++) {
        const u32 bt = base + (u32)t;

        // ---------- load chunk 0 into registers (+injection / outputs) -------
        if (t > 0) wait2(flagrow, bt);     // producers nt=0,1
        XChunk xc;
        #pragma unroll
        for (int s = 0; s < 2; s++) {
            const int k = 32 * s + 2 * q;  // chunk 0: k in 0..63
            if (t == 0) {
                float2 h = *(const float2*)(h0 + k);
                xc.v[s][0] = h.x; xc.v[s][1] = h.y;
                xc.v[s][2] = h.x; xc.v[s][3] = h.y;
                if (nt == 0) {             // states[:,0,:] = s0 (pre-inject)
                    *(float2*)&states[(size_t)bA * Ll * NHID + k] = h;
                    *(float2*)&states[(size_t)bB * Ll * NHID + k] = h;
                }
            } else {
                float2 fa = *(const float2*)&states[((size_t)bA * Ll + t) * NHID + k];
                float2 fb = *(const float2*)&states[((size_t)bB * Ll + t) * NHID + k];
                xc.v[s][0] = fa.x; xc.v[s][1] = fa.y;
                xc.v[s][2] = fb.x; xc.v[s][3] = fb.y;
            }
        }
        {   // injection on slot 0: k = 2q, 2q+1 (< 32 for all lanes)
            const int k = 2 * q;
            float2 yA = *(const float2*)&data[((size_t)bA * Ll + t) * NOBS + k];
            float2 yB = *(const float2*)&data[((size_t)bB * Ll + t) * NOBS + k];
            float dA0 = __fsub_rn(yA.x, xc.v[0][0]);
            float dA1 = __fsub_rn(yA.y, xc.v[0][1]);
            float dB0 = __fsub_rn(yB.x, xc.v[0][2]);
            float dB1 = __fsub_rn(yB.y, xc.v[0][3]);
            if (nt == 0) {
                size_t oA = ((size_t)bA * Ll + t) * NOBS + k;
                size_t oB = ((size_t)bB * Ll + t) * NOBS + k;
                *(float2*)&exps[oA] = make_float2(xc.v[0][0], xc.v[0][1]);
                *(float2*)&exps[oB] = make_float2(xc.v[0][2], xc.v[0][3]);
                *(float2*)&deltas[oA]   = make_float2(dA0, dA1);
                *(float2*)&deltas[oB]   = make_float2(dB0, dB1);
                *(float2*)&partials[oA] = make_float2(dA0, dA1);
                *(float2*)&partials[oB] = make_float2(dB0, dB1);
            }
            xc.v[0][0] = __fadd_rn(xc.v[0][0], dA0);
            xc.v[0][1] = __fadd_rn(xc.v[0][1], dA1);
            xc.v[0][2] = __fadd_rn(xc.v[0][2], dB0);
            xc.v[0][3] = __fadd_rn(xc.v[0][3], dB1);
        }

        // ---------- chunked compute; prefetch next chunk into registers ------
        u64 acc0 = 0, acc1 = 0;            // cols nA, nA+1 (both lanes 0.0f)
        #pragma unroll 1
        for (int c = 0; c < 8; c++) {
            XChunk xn;
            if (c < 7) {                   // poll + LDG chunk c+1 (hidden)
                if (t > 0) wait2(flagrow + 2 * (c + 1), bt);
                #pragma unroll
                for (int s = 0; s < 2; s++) {
                    const int k = 64 * (c + 1) + 32 * s + 2 * q;
                    if (t == 0) {
                        float2 h = *(const float2*)(h0 + k);
                        xn.v[s][0] = h.x; xn.v[s][1] = h.y;
                        xn.v[s][2] = h.x; xn.v[s][3] = h.y;
                        if (nt == 0) {
                            *(float2*)&states[(size_t)bA * Ll * NHID + k] = h;
                            *(float2*)&states[(size_t)bB * Ll * NHID + k] = h;
                        }
                    } else {
                        float2 fa = *(const float2*)&states[((size_t)bA * Ll + t) * NHID + k];
                        float2 fb = *(const float2*)&states[((size_t)bB * Ll + t) * NHID + k];
                        xn.v[s][0] = fa.x; xn.v[s][1] = fa.y;
                        xn.v[s][2] = fb.x; xn.v[s][3] = fb.y;
                    }
                }
            }

            // compute chunk c: k2 ascending (slot 0 j 0..15, slot 1 j 0..15)
            const float* aBase = sA2 + (size_t)c * (32 * 16 * 4);
            #pragma unroll
            for (int s = 0; s < 2; s++) {
                #pragma unroll
                for (int j = 0; j < 16; j++) {
                    const int src = shfl_base + j;
                    float a0 = __shfl_sync(0xffffffffu, xc.v[s][0], src);
                    float a1 = __shfl_sync(0xffffffffu, xc.v[s][1], src);
                    float b0 = __shfl_sync(0xffffffffu, xc.v[s][2], src);
                    float b1 = __shfl_sync(0xffffffffu, xc.v[s][3], src);
                    u64 Xe = pack2(a0, b0);            // (vA[k], vB[k])
                    u64 Xo = pack2(a1, b1);            // (vA[k+1], vB[k+1])
                    const float4 A = *(const float4*)
                        (aBase + ((size_t)((16 * s + j) * 16) + q) * 4);
                    ffma2(acc0, pack2(A.x, A.x), Xe);  // col nA,   k
                    ffma2(acc1, pack2(A.z, A.z), Xe);  // col nA+1, k
                    ffma2(acc0, pack2(A.y, A.y), Xo);  // col nA,   k+1
                    ffma2(acc1, pack2(A.w, A.w), Xo);  // col nA+1, k+1
                }
            }

            if (c < 7) xc = xn;            // register double-buffer swap
        }

        // ---------- tanh + writes -------------------------------------------
        float z0a, z0b, z1a, z1b;
        unpack2(acc0, z0a, z0b);           // (bA,nA), (bB,nA)
        unpack2(acc1, z1a, z1b);           // (bA,nA+1), (bB,nA+1)
        const float h00 = tanh_xla(z0a);
        const float h10 = tanh_xla(z1a);
        const float h01 = tanh_xla(z0b);
        const float h11 = tanh_xla(z1b);

        float* so = states + ((size_t)t + 1) * NHID + nA;
        *(float2*)(so + (size_t)bA * Ll * NHID) = make_float2(h00, h10);
        *(float2*)(so + (size_t)bB * Ll * NHID) = make_float2(h01, h11);

        if (t == NSTEPS - 1 && nt == 0) {  // nA, nA+1 < 32 here
            size_t oA = ((size_t)bA * Ll + (Ll - 1)) * NOBS + nA;
            size_t oB = ((size_t)bB * Ll + (Ll - 1)) * NOBS + nA;
            size_t dIA = ((size_t)bA * Ll + (Ll - 2)) * NOBS + nA;
            size_t dIB = ((size_t)bB * Ll + (Ll - 2)) * NOBS + nA;
            exps[oA] = h00; exps[oA + 1] = h10;
            exps[oB] = h01; exps[oB + 1] = h11;
            float dAx = __fsub_rn(data[dIA],     h00);
            float dAy = __fsub_rn(data[dIA + 1], h10);
            float dBx = __fsub_rn(data[dIB],     h01);
            float dBy = __fsub_rn(data[dIB + 1], h11);
            deltas[oA] = dAx; deltas[oA + 1] = dAy;
            deltas[oB] = dBx; deltas[oB + 1] = dBy;
            partials[oA] = dAx; partials[oA + 1] = dAy;
            partials[oB] = dBx; partials[oB + 1] = dBy;
        }

        // ---------- publish this warp's progress ----------------------------
        if (t < NSTEPS - 1) {
            __syncwarp();                  // order all lanes' STGs before release
            if (l == 0)
                asm volatile("red.global.release.gpu.add.u32 [%0], %1;"
                             :: "l"(myflag), "r"(1u) : "memory");
        }
    }
}

// ---------------------------------------------------------------------------
extern "C" void kernel_launch(void* const* d_in, const int* in_sizes, int n_in,
                              void* d_out, int out_size) {
    const float* data = (const float*)d_in[0];  // [128,2048,32]
    const float* A    = (const float*)d_in[1];  // [512,512]
    const float* h0   = (const float*)d_in[2];  // [1,512]
    // d_in[3] = prob (0) -> dropout identity

    float* out      = (float*)d_out;
    float* exps     = out;
    float* states   = exps   + (size_t)Bb * Ll * NOBS;
    float* deltas   = states + (size_t)Bb * Ll * NHID;
    float* partials = deltas + (size_t)Bb * Ll * NOBS;

    cudaFuncSetAttribute(ptf_persistent,
                         cudaFuncAttributeMaxDynamicSharedMemorySize, SMEM_BYTES);
    ptf_persistent<<<NCTA, NTHREADS, SMEM_BYTES>>>(data, A, h0,
                                                   exps, states, deltas, partials);
}